// round 3
// baseline (speedup 1.0000x reference)
#include <cuda_runtime.h>
#include <cstdint>

#define BB   16
#define NSS  128
#define TT   64
#define DD   512
#define HH   512
#define NB_LSTM 128

// ---------------- scratch (device globals) ----------------
__device__ float g_attn_feat[BB * NSS * HH];
__device__ float g_hop_feat [BB * NSS * HH];
__device__ float g_xcat     [TT * BB * DD];      // row = t*16+b
__device__ float g_X        [TT * BB * 4 * HH];  // gate preacts
__device__ float g_qa       [BB * TT * HH];      // row = b*64+t
__device__ float g_qb       [BB * TT * HH];
__device__ float g_qw       [BB * TT * HH];
__device__ float g_hbuf     [2][BB * HH];
__device__ unsigned g_cnt   [TT + 1];

// ---------------- helpers ----------------
__device__ __forceinline__ float fast_tanh(float x) {
    float e, r;
    asm("ex2.approx.f32 %0, %1;" : "=f"(e) : "f"(x * 2.885390081777927f));
    asm("rcp.approx.f32 %0, %1;" : "=f"(r) : "f"(e + 1.0f));
    return fmaf(-2.0f, r, 1.0f);
}
__device__ __forceinline__ float sigm(float x) { return 1.0f / (1.0f + __expf(-x)); }

// ---------------- tiled SGEMM: C[M,N] = A@B (+bias) ----------------
template<bool TRANSB, bool BIAS>
__global__ void __launch_bounds__(256) sgemm_kernel(
    const float* __restrict__ A, const float* __restrict__ Bm,
    const float* __restrict__ b1, const float* __restrict__ b2,
    float* __restrict__ C, int M, int N, int K)
{
    __shared__ float As[16][68];
    __shared__ float Bs[16][68];
    const int tid = threadIdx.x;
    const int m0 = blockIdx.y * 64, n0 = blockIdx.x * 64;
    const int tx = (tid & 15) << 2, ty = (tid >> 4) << 2;
    const int lr = tid >> 2, lk = (tid & 3) << 2;
    const int bkr = tid >> 4, bnc = (tid & 15) << 2;
    float acc[4][4] = {};

    for (int k0 = 0; k0 < K; k0 += 16) {
        float4 av = *reinterpret_cast<const float4*>(A + (size_t)(m0 + lr) * K + k0 + lk);
        As[lk+0][lr] = av.x; As[lk+1][lr] = av.y; As[lk+2][lr] = av.z; As[lk+3][lr] = av.w;
        if (TRANSB) {
            float4 bv = *reinterpret_cast<const float4*>(Bm + (size_t)(n0 + lr) * K + k0 + lk);
            Bs[lk+0][lr] = bv.x; Bs[lk+1][lr] = bv.y; Bs[lk+2][lr] = bv.z; Bs[lk+3][lr] = bv.w;
        } else {
            float4 bv = *reinterpret_cast<const float4*>(Bm + (size_t)(k0 + bkr) * N + n0 + bnc);
            *reinterpret_cast<float4*>(&Bs[bkr][bnc]) = bv;
        }
        __syncthreads();
#pragma unroll
        for (int kk = 0; kk < 16; kk++) {
            float4 a = *reinterpret_cast<const float4*>(&As[kk][ty]);
            float4 b = *reinterpret_cast<const float4*>(&Bs[kk][tx]);
            acc[0][0] += a.x*b.x; acc[0][1] += a.x*b.y; acc[0][2] += a.x*b.z; acc[0][3] += a.x*b.w;
            acc[1][0] += a.y*b.x; acc[1][1] += a.y*b.y; acc[1][2] += a.y*b.z; acc[1][3] += a.y*b.w;
            acc[2][0] += a.z*b.x; acc[2][1] += a.z*b.y; acc[2][2] += a.z*b.z; acc[2][3] += a.z*b.w;
            acc[3][0] += a.w*b.x; acc[3][1] += a.w*b.y; acc[3][2] += a.w*b.z; acc[3][3] += a.w*b.w;
        }
        __syncthreads();
    }
    float bx=0.f, by=0.f, bz=0.f, bw=0.f;
    if (BIAS) {
        bx = b1[n0+tx+0]+b2[n0+tx+0]; by = b1[n0+tx+1]+b2[n0+tx+1];
        bz = b1[n0+tx+2]+b2[n0+tx+2]; bw = b1[n0+tx+3]+b2[n0+tx+3];
    }
#pragma unroll
    for (int i = 0; i < 4; i++) {
        float4 o = {acc[i][0]+bx, acc[i][1]+by, acc[i][2]+bz, acc[i][3]+bw};
        *reinterpret_cast<float4*>(C + (size_t)(m0+ty+i) * N + n0 + tx) = o;
    }
}

// ---------------- prep: xcat + maxpool + h0 ----------------
__global__ void prep_kernel(const float* __restrict__ attn_mem,
                            const float* __restrict__ lstm_in,
                            const float* __restrict__ init_h,
                            const int* __restrict__ msz)
{
    const int t = blockIdx.x, b = blockIdx.y, d = threadIdx.x;
    if (t == 0) {
        const int ms = msz[b];
        float m = -3.0e38f;
        for (int n = 0; n < ms; n++)
            m = fmaxf(m, attn_mem[((size_t)b * NSS + n) * DD + d]);
        g_xcat[(size_t)b * DD + d] = m;
        g_hbuf[0][b * HH + d] = init_h[d];
    } else {
        g_xcat[((size_t)t * BB + b) * DD + d] =
            lstm_in[((size_t)b * (TT - 1) + (t - 1)) * DD + d];
    }
}

// ---------------- persistent LSTM: 128 CTAs, per-step grid barrier ----------------
__global__ void __launch_bounds__(256) lstm_kernel(const float* __restrict__ Whh,
                                                   const float* __restrict__ init_c)
{
    __shared__ float h_sm[16][516];
    __shared__ float red[4][16][16];
    __shared__ float gsm[16][16];
    __shared__ float c_sm[16][4];

    const int tid = threadIdx.x;
    const int hd0 = blockIdx.x * 4;
    const int kc = tid >> 6;
    const int r  = (tid >> 2) & 15;
    const int bq = tid & 3;
    const int grow = (r >> 2) * HH + hd0 + (r & 3);
    const float* __restrict__ wrow = Whh + (size_t)grow * HH + kc * 128;

    if (tid < 64) { int b = tid >> 2, l = tid & 3; c_sm[b][l] = init_c[hd0 + l]; }

    for (int s = 0; s < TT; s++) {
        __syncthreads();
        const float4* hb = reinterpret_cast<const float4*>(g_hbuf[s & 1]);
        for (int i = tid; i < (BB * HH) / 4; i += 256) {
            float4 hv = __ldcg(hb + i);
            int b = i >> 7, k = (i & 127) << 2;
            *reinterpret_cast<float4*>(&h_sm[b][k]) = hv;
        }
        __syncthreads();

        float a0=0.f, a1=0.f, a2=0.f, a3=0.f;
        const int kb = kc * 128;
#pragma unroll 8
        for (int j = 0; j < 128; j += 4) {
            float4 w4 = *reinterpret_cast<const float4*>(wrow + j);
            float4 h0 = *reinterpret_cast<const float4*>(&h_sm[bq +  0][kb + j]);
            float4 h1 = *reinterpret_cast<const float4*>(&h_sm[bq +  4][kb + j]);
            float4 h2 = *reinterpret_cast<const float4*>(&h_sm[bq +  8][kb + j]);
            float4 h3 = *reinterpret_cast<const float4*>(&h_sm[bq + 12][kb + j]);
            a0 += w4.x*h0.x + w4.y*h0.y + w4.z*h0.z + w4.w*h0.w;
            a1 += w4.x*h1.x + w4.y*h1.y + w4.z*h1.z + w4.w*h1.w;
            a2 += w4.x*h2.x + w4.y*h2.y + w4.z*h2.z + w4.w*h2.w;
            a3 += w4.x*h3.x + w4.y*h3.y + w4.z*h3.z + w4.w*h3.w;
        }
        red[kc][bq +  0][r] = a0;
        red[kc][bq +  4][r] = a1;
        red[kc][bq +  8][r] = a2;
        red[kc][bq + 12][r] = a3;
        __syncthreads();
        {
            int b2 = tid >> 4, r2 = tid & 15;
            gsm[b2][r2] = red[0][b2][r2] + red[1][b2][r2] + red[2][b2][r2] + red[3][b2][r2]
                + g_X[((size_t)s * BB + b2) * (4 * HH) + (r2 >> 2) * HH + hd0 + (r2 & 3)];
        }
        __syncthreads();
        if (tid < 64) {
            int b = tid >> 2, l = tid & 3;
            float gi = gsm[b][0 + l], gf = gsm[b][4 + l];
            float gg = gsm[b][8 + l], go = gsm[b][12 + l];
            float c = sigm(gf) * c_sm[b][l] + sigm(gi) * fast_tanh(gg);
            float h = sigm(go) * fast_tanh(c);
            c_sm[b][l] = c;
            g_hbuf[(s + 1) & 1][b * HH + hd0 + l] = h;
            g_qa[((size_t)b * TT + s) * HH + hd0 + l] = h;
        }
        __threadfence();
        __syncthreads();
        if (tid == 0) {
            atomicAdd(&g_cnt[s], 1u);
            while (*((volatile unsigned*)&g_cnt[s]) < (unsigned)NB_LSTM) { __nanosleep(64); }
        }
        __syncthreads();
    }
    if (tid == 0) {
        unsigned t = atomicAdd(&g_cnt[TT], 1u);
        if (t == (unsigned)(NB_LSTM - 1)) {
            for (int i = 0; i <= TT; i++) g_cnt[i] = 0u;
            __threadfence();
        }
    }
}

// ---------------- hop: score+mask+softmax+weighted-sum ----------------
__global__ void __launch_bounds__(256) hop_kernel(
    const float* __restrict__ qw, const float* __restrict__ feat,
    const float* __restrict__ v, const int* __restrict__ msz,
    float* __restrict__ qout)
{
    __shared__ float qsm[HH];
    __shared__ float vsm[HH];
    __shared__ float p[NSS];
    const int t = blockIdx.x, b = blockIdx.y, tid = threadIdx.x;
    const float* qrow = qw + ((size_t)b * TT + t) * HH;
    qsm[tid] = qrow[tid]; qsm[tid + 256] = qrow[tid + 256];
    vsm[tid] = v[tid];    vsm[tid + 256] = v[tid + 256];
    __syncthreads();

    const int wid = tid >> 5, lane = tid & 31;
    const int ms = msz[b];
    for (int n = wid; n < NSS; n += 8) {
        const float* f = feat + ((size_t)b * NSS + n) * HH;
        float s = 0.f;
#pragma unroll 4
        for (int j = 0; j < 16; j++) {
            int k = lane + (j << 5);
            s += vsm[k] * fast_tanh(f[k] + qsm[k]);
        }
#pragma unroll
        for (int o = 16; o; o >>= 1) s += __shfl_xor_sync(0xffffffffu, s, o);
        if (lane == 0) p[n] = (n < ms) ? s : -1e30f;
    }
    __syncthreads();
    if (tid < 32) {
        float m = fmaxf(fmaxf(p[tid], p[tid+32]), fmaxf(p[tid+64], p[tid+96]));
#pragma unroll
        for (int o = 16; o; o >>= 1) m = fmaxf(m, __shfl_xor_sync(0xffffffffu, m, o));
        float s = 0.f, e[4];
#pragma unroll
        for (int i = 0; i < 4; i++) { e[i] = __expf(p[tid+32*i] - m); s += e[i]; }
#pragma unroll
        for (int o = 16; o; o >>= 1) s += __shfl_xor_sync(0xffffffffu, s, o);
        float inv = 1.f / s;
#pragma unroll
        for (int i = 0; i < 4; i++) p[tid+32*i] = e[i] * inv;
    }
    __syncthreads();
    for (int h = tid; h < HH; h += 256) {
        float acc = 0.f;
#pragma unroll 4
        for (int n = 0; n < NSS; n++)
            acc += p[n] * feat[((size_t)b * NSS + n) * HH + h];
        qout[((size_t)b * TT + t) * HH + h] = acc;
    }
}

// ---------------- final score (unmasked) ----------------
__global__ void __launch_bounds__(256) final_kernel(
    const float* __restrict__ qw, const float* __restrict__ feat,
    const float* __restrict__ v, float* __restrict__ out)
{
    __shared__ float qsm[HH];
    __shared__ float vsm[HH];
    const int t = blockIdx.x, b = blockIdx.y, tid = threadIdx.x;
    const float* qrow = qw + ((size_t)b * TT + t) * HH;
    qsm[tid] = qrow[tid]; qsm[tid + 256] = qrow[tid + 256];
    vsm[tid] = v[tid];    vsm[tid + 256] = v[tid + 256];
    __syncthreads();
    const int wid = tid >> 5, lane = tid & 31;
    for (int n = wid; n < NSS; n += 8) {
        const float* f = feat + ((size_t)b * NSS + n) * HH;
        float s = 0.f;
#pragma unroll 4
        for (int j = 0; j < 16; j++) {
            int k = lane + (j << 5);
            s += vsm[k] * fast_tanh(f[k] + qsm[k]);
        }
#pragma unroll
        for (int o = 16; o; o >>= 1) s += __shfl_xor_sync(0xffffffffu, s, o);
        if (lane == 0) out[(((size_t)b * TT) + t) * NSS + n] = s;
    }
}

extern "C" void kernel_launch(void* const* d_in, const int* in_sizes, int n_in,
                              void* d_out, int out_size)
{
    const float* attn_mem = (const float*)d_in[0];
    const float* lstm_in  = (const float*)d_in[1];
    const float* init_h   = (const float*)d_in[2];
    const float* init_c   = (const float*)d_in[3];
    const float* Wih      = (const float*)d_in[4];
    const float* Whh      = (const float*)d_in[5];
    const float* bih      = (const float*)d_in[6];
    const float* bhh      = (const float*)d_in[7];
    const float* attn_wm  = (const float*)d_in[8];
    const float* attn_wq  = (const float*)d_in[9];
    const float* attn_v   = (const float*)d_in[10];
    const float* hop_wm   = (const float*)d_in[11];
    const float* hop_wq   = (const float*)d_in[12];
    const float* hop_v    = (const float*)d_in[13];
    const int*   msz      = (const int*)d_in[14];
    float* out = (float*)d_out;

    float *afeat, *hfeat, *xcat, *X, *qa, *qb, *qwb;
    cudaGetSymbolAddress((void**)&afeat, g_attn_feat);
    cudaGetSymbolAddress((void**)&hfeat, g_hop_feat);
    cudaGetSymbolAddress((void**)&xcat,  g_xcat);
    cudaGetSymbolAddress((void**)&X,     g_X);
    cudaGetSymbolAddress((void**)&qa,    g_qa);
    cudaGetSymbolAddress((void**)&qb,    g_qb);
    cudaGetSymbolAddress((void**)&qwb,   g_qw);

    prep_kernel<<<dim3(TT, BB), DD>>>(attn_mem, lstm_in, init_h, msz);
    sgemm_kernel<false,false><<<dim3(8, 32), 256>>>(attn_mem, attn_wm, nullptr, nullptr, afeat, BB*NSS, HH, DD);
    sgemm_kernel<false,false><<<dim3(8, 32), 256>>>(attn_mem, hop_wm,  nullptr, nullptr, hfeat, BB*NSS, HH, DD);
    sgemm_kernel<true, true ><<<dim3(32, 16), 256>>>(xcat, Wih, bih, bhh, X, TT*BB, 4*HH, DD);
    lstm_kernel<<<NB_LSTM, 256>>>(Whh, init_c);
    // hop 1
    sgemm_kernel<false,false><<<dim3(8, 16), 256>>>(qa, hop_wq, nullptr, nullptr, qwb, BB*TT, HH, HH);
    hop_kernel<<<dim3(TT, BB), 256>>>(qwb, hfeat, hop_v, msz, qb);
    // hop 2
    sgemm_kernel<false,false><<<dim3(8, 16), 256>>>(qb, hop_wq, nullptr, nullptr, qwb, BB*TT, HH, HH);
    hop_kernel<<<dim3(TT, BB), 256>>>(qwb, hfeat, hop_v, msz, qa);
    // final
    sgemm_kernel<false,false><<<dim3(8, 16), 256>>>(qa, attn_wq, nullptr, nullptr, qwb, BB*TT, HH, HH);
    final_kernel<<<dim3(TT, BB), 256>>>(qwb, afeat, attn_v, out);
}